// round 1
// baseline (speedup 1.0000x reference)
#include <cuda_runtime.h>
#include <cstdint>
#include <math.h>

#define S_LEN 768
#define EMB   128
#define HDIM  256
#define G4    1024
#define MLPD  128

// ---------------- scratch (static device memory; no allocation) ----------------
__device__ float d_x  [S_LEN * EMB];
__device__ float d_gxF[S_LEN * G4];
__device__ float d_gxB[S_LEN * G4];
__device__ float d_h0 [S_LEN * 2 * HDIM];
__device__ float d_h1 [S_LEN * 2 * HDIM];
__device__ float d_hA [S_LEN * MLPD];
__device__ float d_hB [S_LEN * MLPD];

// ---------------- fast activations ----------------
__device__ __forceinline__ float sigmoidf_fast(float x) {
    return __fdividef(1.f, 1.f + __expf(-x));
}
__device__ __forceinline__ float tanhf_fast(float x) {
    float e = __expf(-2.f * fabsf(x));
    float r = __fdividef(1.f - e, 1.f + e);
    return copysignf(r, x);
}

// ---------------- cluster helpers ----------------
__device__ __forceinline__ uint32_t smem_u32(const void* p) {
    uint32_t a;
    asm("{ .reg .u64 t; cvta.to.shared.u64 t, %1; cvt.u32.u64 %0, t; }"
        : "=r"(a) : "l"(p));
    return a;
}
__device__ __forceinline__ void st_cluster_f32(uint32_t local_addr, uint32_t rank, float v) {
    uint32_t rem;
    asm volatile("mapa.shared::cluster.u32 %0, %1, %2;"
                 : "=r"(rem) : "r"(local_addr), "r"(rank));
    asm volatile("st.shared::cluster.f32 [%0], %1;" :: "r"(rem), "f"(v) : "memory");
}
__device__ __forceinline__ void cluster_sync_() {
    asm volatile("barrier.cluster.arrive.aligned;" ::: "memory");
    asm volatile("barrier.cluster.wait.aligned;" ::: "memory");
}
__device__ __forceinline__ uint32_t cluster_rank_() {
    uint32_t r; asm("mov.u32 %0, %%cluster_ctarank;" : "=r"(r)); return r;
}

// ---------------- embedding gather ----------------
__global__ void embed_kernel(const int* __restrict__ widx, const int* __restrict__ pidx,
                             const float* __restrict__ Ww, const float* __restrict__ Wp) {
    int s = blockIdx.x, f = threadIdx.x;
    float v = (f < 100) ? Ww[widx[s] * 100 + f] : Wp[pidx[s] * 28 + (f - 100)];
    d_x[s * EMB + f] = v;
}

// ---------------- generic C[M,N] = A[M,K] * B[N,K]^T + bias1 + bias2 ----------------
__global__ __launch_bounds__(256) void gemm_bias_kernel(
    const float* __restrict__ A, int lda,
    const float* __restrict__ B, int ldb,
    const float* __restrict__ bias1, const float* __restrict__ bias2,
    float* __restrict__ C, int ldc,
    int M, int N, int K)
{
    __shared__ __align__(16) float As[16][68];
    __shared__ __align__(16) float Bs[16][68];
    int tid = threadIdx.x;
    int bx = blockIdx.x, by = blockIdx.y;
    int tx = tid & 15, ty = tid >> 4;
    int m0 = by * 64 + ty * 4;
    int n0 = bx * 64 + tx * 4;
    float acc[4][4] = {};

    for (int k0 = 0; k0 < K; k0 += 16) {
#pragma unroll
        for (int i = 0; i < 4; i++) {
            int idx = tid + i * 256;
            int r = idx >> 4, kk = idx & 15;
            int col = k0 + kk;
            int mrow = by * 64 + r;
            int nrow = bx * 64 + r;
            As[kk][r] = (mrow < M && col < K) ? A[mrow * lda + col] : 0.f;
            Bs[kk][r] = (nrow < N && col < K) ? B[nrow * ldb + col] : 0.f;
        }
        __syncthreads();
#pragma unroll
        for (int kk = 0; kk < 16; kk++) {
            float4 av = *reinterpret_cast<const float4*>(&As[kk][ty * 4]);
            float4 bv = *reinterpret_cast<const float4*>(&Bs[kk][tx * 4]);
            float a[4] = {av.x, av.y, av.z, av.w};
            float b[4] = {bv.x, bv.y, bv.z, bv.w};
#pragma unroll
            for (int i = 0; i < 4; i++)
#pragma unroll
                for (int j = 0; j < 4; j++)
                    acc[i][j] = fmaf(a[i], b[j], acc[i][j]);
        }
        __syncthreads();
    }
#pragma unroll
    for (int i = 0; i < 4; i++)
#pragma unroll
        for (int j = 0; j < 4; j++) {
            int r = m0 + i, c = n0 + j;
            if (r < M && c < N) {
                float bv = 0.f;
                if (bias1) bv += bias1[c];
                if (bias2) bv += bias2[c];
                C[r * ldc + c] = acc[i][j] + bv;
            }
        }
}

// ---------------- BiLSTM recurrence: 2 clusters x 8 CTAs x 256 threads ----------------
// Cluster 0 = forward dir, cluster 1 = backward dir.
// CTA owns 32 hidden units (128 gate rows). Thread (rl = tid>>1, hf = tid&1)
// holds 128 Whh weights in registers for gate row `grow`, half `hf`.
__global__ void __cluster_dims__(8, 1, 1) __launch_bounds__(256, 1)
lstm_kernel(const float* __restrict__ WhhF, const float* __restrict__ WhhB,
            const float* __restrict__ gxF,  const float* __restrict__ gxB,
            float* __restrict__ hout)
{
    __shared__ __align__(16) float hbuf[2][264];   // [0,128) lower half, [132,260) upper half
    __shared__ float gates[128];

    int tid   = threadIdx.x;
    uint32_t crank = cluster_rank_();
    int dir   = blockIdx.x >> 3;           // 0 = fwd, 1 = bwd
    const float* Whh = dir ? WhhB : WhhF;
    const float* gx  = dir ? gxB  : gxF;

    int rl   = tid >> 1;                   // local gate row 0..127
    int hf   = tid & 1;                    // which half of the 256 h values
    int gate = rl >> 5, unit = rl & 31;
    int grow = gate * 256 + (int)crank * 32 + unit;

    // register-resident weights
    float w[128];
    const float4* wsrc = reinterpret_cast<const float4*>(Whh + grow * 256 + hf * 128);
#pragma unroll
    for (int k = 0; k < 32; k++) {
        float4 v = wsrc[k];
        w[4*k] = v.x; w[4*k+1] = v.y; w[4*k+2] = v.z; w[4*k+3] = v.w;
    }

    for (int i = tid; i < 2 * 264; i += 256) (&hbuf[0][0])[i] = 0.f;
    __syncthreads();
    cluster_sync_();

    float cstate = 0.f;
    uint32_t hbase = smem_u32(&hbuf[0][0]);

    for (int t = 0; t < S_LEN; t++) {
        int s = dir ? (S_LEN - 1 - t) : t;
        float gxv = gx[s * G4 + grow];

        const float4* hv = reinterpret_cast<const float4*>(&hbuf[t & 1][hf * 132]);
        float a0 = 0.f, a1 = 0.f, a2 = 0.f, a3 = 0.f;
#pragma unroll
        for (int k = 0; k < 32; k++) {
            float4 h4 = hv[k];
            a0 = fmaf(w[4*k],   h4.x, a0);
            a1 = fmaf(w[4*k+1], h4.y, a1);
            a2 = fmaf(w[4*k+2], h4.z, a2);
            a3 = fmaf(w[4*k+3], h4.w, a3);
        }
        float acc = (a0 + a1) + (a2 + a3);
        acc += __shfl_xor_sync(0xffffffffu, acc, 1);
        if (hf == 0) gates[rl] = gxv + acc;
        __syncthreads();

        if (tid < 32) {
            int u = tid;
            float gi = sigmoidf_fast(gates[u]);
            float gf = sigmoidf_fast(gates[32 + u]);
            float gg = tanhf_fast   (gates[64 + u]);
            float go = sigmoidf_fast(gates[96 + u]);
            cstate   = gf * cstate + gi * gg;
            float hn = go * tanhf_fast(cstate);

            int g = (int)crank * 32 + u;
            uint32_t off = (uint32_t)(((t + 1) & 1) * 264 + (g < 128 ? g : 132 + (g - 128))) * 4u;
#pragma unroll
            for (int p = 0; p < 8; p++)
                st_cluster_f32(hbase + off, (uint32_t)p, hn);

            hout[s * 512 + dir * 256 + g] = hn;
        }
        cluster_sync_();   // orders remote h stores, doubles as CTA barrier
    }
}

// ---------------- pairwise scorer ----------------
__global__ __launch_bounds__(256) void scorer_kernel(
    const float* __restrict__ hA, const float* __restrict__ hB,
    const float* __restrict__ W2, const float* __restrict__ b2,
    float* __restrict__ out)
{
    __shared__ float sA[16][129];
    __shared__ float sB[16][129];
    __shared__ float sw[128];
    int tid = threadIdx.x;
    int j0 = blockIdx.x * 16, i0 = blockIdx.y * 16;

    for (int idx = tid; idx < 16 * 128; idx += 256) {
        int r = idx >> 7, k = idx & 127;
        sA[r][k] = hA[(i0 + r) * MLPD + k];
        sB[r][k] = hB[(j0 + r) * MLPD + k];
    }
    if (tid < 128) sw[tid] = W2[tid];
    __syncthreads();

    int tx = tid & 15, ty = tid >> 4;
    float acc = b2[0];
#pragma unroll 4
    for (int k = 0; k < 128; k++) {
        float v = sA[ty][k] + sB[tx][k];
        acc = fmaf(sw[k], tanhf_fast(v), acc);
    }
    int i = i0 + ty, j = j0 + tx;
    out[i * S_LEN + j] = (i == j) ? 0.f : acc;
}

// ---------------- launch ----------------
extern "C" void kernel_launch(void* const* d_in, const int* in_sizes, int n_in,
                              void* d_out, int out_size)
{
    // d_in[2] may be the python-int sentence_len (scalar). Detect via size.
    int base = (in_sizes[2] < 1000) ? 3 : 2;

    const int* widx = (const int*)d_in[0];
    const int* pidx = (const int*)d_in[1];
    const float* W_word = (const float*)d_in[base + 0];
    const float* W_pos  = (const float*)d_in[base + 1];
    // order: l0f, l0b, l1f, l1b
    const float *Wih[4], *Whh[4], *bih[4], *bhh[4];
    for (int i = 0; i < 4; i++) {
        Wih[i] = (const float*)d_in[base + 2 + 4 * i];
        Whh[i] = (const float*)d_in[base + 3 + 4 * i];
        bih[i] = (const float*)d_in[base + 4 + 4 * i];
        bhh[i] = (const float*)d_in[base + 5 + 4 * i];
    }
    const float* W1 = (const float*)d_in[base + 18];
    const float* b1 = (const float*)d_in[base + 19];
    const float* W2 = (const float*)d_in[base + 20];
    const float* b2 = (const float*)d_in[base + 21];
    float* out = (float*)d_out;

    float *xp, *gxF, *gxB, *h0, *h1, *hA, *hB;
    cudaGetSymbolAddress((void**)&xp,  d_x);
    cudaGetSymbolAddress((void**)&gxF, d_gxF);
    cudaGetSymbolAddress((void**)&gxB, d_gxB);
    cudaGetSymbolAddress((void**)&h0,  d_h0);
    cudaGetSymbolAddress((void**)&h1,  d_h1);
    cudaGetSymbolAddress((void**)&hA,  d_hA);
    cudaGetSymbolAddress((void**)&hB,  d_hB);

    // 1) embeddings
    embed_kernel<<<S_LEN, EMB>>>(widx, pidx, W_word, W_pos);

    // 2) layer-0 input GEMMs: gx = x @ Wih^T + bih + bhh   [768,1024]
    dim3 gGX(G4 / 64, S_LEN / 64);
    gemm_bias_kernel<<<gGX, 256>>>(xp, EMB, Wih[0], EMB, bih[0], bhh[0], gxF, G4, S_LEN, G4, EMB);
    gemm_bias_kernel<<<gGX, 256>>>(xp, EMB, Wih[1], EMB, bih[1], bhh[1], gxB, G4, S_LEN, G4, EMB);

    // 3) layer-0 recurrence (fwd + bwd concurrently)
    lstm_kernel<<<16, 256>>>(Whh[0], Whh[1], gxF, gxB, h0);

    // 4) layer-1 input GEMMs: gx = h0 @ Wih^T + biases  (K = 512)
    gemm_bias_kernel<<<gGX, 256>>>(h0, 512, Wih[2], 512, bih[2], bhh[2], gxF, G4, S_LEN, G4, 512);
    gemm_bias_kernel<<<gGX, 256>>>(h0, 512, Wih[3], 512, bih[3], bhh[3], gxB, G4, S_LEN, G4, 512);

    // 5) layer-1 recurrence
    lstm_kernel<<<16, 256>>>(Whh[2], Whh[3], gxF, gxB, h1);

    // 6) scorer projections: hA = h1 @ W1[:, :512]^T + b1 ; hB = h1 @ W1[:, 512:]^T
    dim3 gAB(MLPD / 64, S_LEN / 64);
    gemm_bias_kernel<<<gAB, 256>>>(h1, 512, W1,       1024, b1,      nullptr, hA, MLPD, S_LEN, MLPD, 512);
    gemm_bias_kernel<<<gAB, 256>>>(h1, 512, W1 + 512, 1024, nullptr, nullptr, hB, MLPD, S_LEN, MLPD, 512);

    // 7) pairwise scores [768,768], diag = 0
    scorer_kernel<<<dim3(S_LEN / 16, S_LEN / 16), 256>>>(hA, hB, W2, b2, out);
}